// round 7
// baseline (speedup 1.0000x reference)
#include <cuda_runtime.h>

#define B_TOTAL 262144
#define TPB 128
#define ROWS_CTA 256
#define NBLK (B_TOTAL / ROWS_CTA)          // 1024

// Per-layer smem: bias[64] | c0[64] | Wf[64][64] row-major
#define WL_FLOATS (64 + 64 + 4096)         // 4224
#define W_TOTAL (3 * WL_FLOATS)            // 12672
#define SLOT_FLOATS (ROWS_CTA * 64)        // 16384, stride-64 + 16B-chunk XOR swizzle
#define SMEM_FLOATS (W_TOTAL + SLOT_FLOATS)  // 29056
#define SMEM_BYTES (SMEM_FLOATS * 4)       // 116224 B -> 2 CTAs/SM (232448 <= 228KB)

typedef unsigned long long ull;

__device__ __forceinline__ void ffma2(ull& d, ull a, ull b) {
    asm("fma.rn.f32x2 %0, %1, %2, %0;" : "+l"(d) : "l"(a), "l"(b));
}
__device__ __forceinline__ float pairsum(ull v) {
    float lo, hi;
    asm("mov.b64 {%0, %1}, %2;" : "=f"(lo), "=f"(hi) : "l"(v));
    return lo + hi;
}
__device__ __forceinline__ ull pack2(float lo, float hi) {
    ull r;
    asm("mov.b64 %0, {%1, %2};" : "=l"(r) : "f"(lo), "f"(hi));
    return r;
}
// Zero pair lanes per relu-mask bits (2q, 2q+1).
__device__ __forceinline__ ull maskpair(ull v, ull m, int q) {
    ull mm = (((m >> (2 * q)) & 1ull) * 0x00000000FFFFFFFFull)
           | (((m >> (2 * q + 1)) & 1ull) * 0xFFFFFFFF00000000ull);
    return v & mm;
}
// Swizzled float-offset of 64-bit pair q within a 64-float staging row:
// 16B chunk (q>>1) XOR (row&15); low/high half selected by q&1.
__device__ __forceinline__ int st_pair_off(int rm, int q) {
    return (((q >> 1) ^ rm) << 2) + ((q & 1) << 1);
}

// ---------------------------------------------------------------------------
// Dual-row sequential matvec (cuBLAS-exact rounding, mask-determining).
// Per-row chain bit-identical to R3/R4/R6; two rows share weight loads.
// bias/c0 read from smem (NOT __ldg -- the R6 reg-pressure suspect).
// ---------------------------------------------------------------------------
__device__ __forceinline__ void matvec_seq_dual(
    const float* __restrict__ Wf, const float* __restrict__ bias,
    const float* __restrict__ c0, float t,
    const float2* __restrict__ x0, const float2* __restrict__ x1,
    float* __restrict__ st0, float* __restrict__ st1, int rm,
    ull& m0, ull& m1) {
#pragma unroll 2
    for (int j = 0; j < 64; j += 2) {
        float c0j = t * c0[j], c1j = t * c0[j + 1];
        float a00 = c0j, a01 = c1j;
        float a10 = c0j, a11 = c1j;
        const float4* w0 = (const float4*)(Wf + j * 64);
        const float4* w1 = (const float4*)(Wf + (j + 1) * 64);
#pragma unroll
        for (int q = 0; q < 16; q++) {
            float4 v0 = w0[q];
            float4 v1 = w1[q];
            float2 xa0 = x0[2 * q], xb0 = x0[2 * q + 1];
            float2 xa1 = x1[2 * q], xb1 = x1[2 * q + 1];
            a00 = fmaf(xa0.x, v0.x, a00); a00 = fmaf(xa0.y, v0.y, a00);
            a00 = fmaf(xb0.x, v0.z, a00); a00 = fmaf(xb0.y, v0.w, a00);
            a01 = fmaf(xa0.x, v1.x, a01); a01 = fmaf(xa0.y, v1.y, a01);
            a01 = fmaf(xb0.x, v1.z, a01); a01 = fmaf(xb0.y, v1.w, a01);
            a10 = fmaf(xa1.x, v0.x, a10); a10 = fmaf(xa1.y, v0.y, a10);
            a10 = fmaf(xb1.x, v0.z, a10); a10 = fmaf(xb1.y, v0.w, a10);
            a11 = fmaf(xa1.x, v1.x, a11); a11 = fmaf(xa1.y, v1.y, a11);
            a11 = fmaf(xb1.x, v1.z, a11); a11 = fmaf(xb1.y, v1.w, a11);
        }
        float s00 = a00 + bias[j], s01 = a01 + bias[j + 1];
        float s10 = a10 + bias[j], s11 = a11 + bias[j + 1];
        if (s00 > 0.0f) m0 |= (1ull << j); else s00 = 0.0f;
        if (s01 > 0.0f) m0 |= (1ull << (j + 1)); else s01 = 0.0f;
        if (s10 > 0.0f) m1 |= (1ull << j); else s10 = 0.0f;
        if (s11 > 0.0f) m1 |= (1ull << (j + 1)); else s11 = 0.0f;
        int off = st_pair_off(rm, j >> 1);
        *(ull*)(st0 + off) = pack2(s00, s01);
        *(ull*)(st1 + off) = pack2(s10, s11);
    }
}

// ---------------------------------------------------------------------------
// Dual-row FFMA2 dot matvec (continuous paths): out = W x (+ bias + t*c0).
// ---------------------------------------------------------------------------
template <int WITH_AFFINE>
__device__ __forceinline__ void matvec_dot_dual(
    const float* __restrict__ Wf, const float* __restrict__ bias,
    const float* __restrict__ c0, float t,
    const ull* __restrict__ x0, const ull* __restrict__ x1,
    float* __restrict__ st0, float* __restrict__ st1, int rm) {
#pragma unroll 1
    for (int j = 0; j < 64; j += 2) {
        ull a00 = 0ull, a01 = 0ull, a10 = 0ull, a11 = 0ull;
        const ulonglong2* w0 = (const ulonglong2*)(Wf + j * 64);
        const ulonglong2* w1 = (const ulonglong2*)(Wf + (j + 1) * 64);
#pragma unroll
        for (int q = 0; q < 16; q++) {
            ulonglong2 v0 = w0[q];
            ulonglong2 v1 = w1[q];
            ffma2(a00, v0.x, x0[2 * q]); ffma2(a00, v0.y, x0[2 * q + 1]);
            ffma2(a01, v1.x, x0[2 * q]); ffma2(a01, v1.y, x0[2 * q + 1]);
            ffma2(a10, v0.x, x1[2 * q]); ffma2(a10, v0.y, x1[2 * q + 1]);
            ffma2(a11, v1.x, x1[2 * q]); ffma2(a11, v1.y, x1[2 * q + 1]);
        }
        float s00 = pairsum(a00), s01 = pairsum(a01);
        float s10 = pairsum(a10), s11 = pairsum(a11);
        if (WITH_AFFINE) {
            float b0j = bias[j] + t * c0[j];
            float b1j = bias[j + 1] + t * c0[j + 1];
            s00 += b0j; s01 += b1j; s10 += b0j; s11 += b1j;
        }
        int off = st_pair_off(rm, j >> 1);
        *(ull*)(st0 + off) = pack2(s00, s01);
        *(ull*)(st1 + off) = pack2(s10, s11);
    }
}

__global__ void __launch_bounds__(TPB, 1)
ode_kernel(const float* __restrict__ tptr, const float* __restrict__ z,
           const float* __restrict__ e,
           const float* __restrict__ W0, const float* __restrict__ b0,
           const float* __restrict__ W1, const float* __restrict__ b1,
           const float* __restrict__ W2, const float* __restrict__ b2,
           float* __restrict__ zdot, float* __restrict__ negdiv) {
    extern __shared__ float sm[];
    const int tid = threadIdx.x;

    // ---- Stage weights + bias + t-column per layer ----
    {
        const float* Wg[3] = {W0, W1, W2};
        const float* bgv[3] = {b0, b1, b2};
#pragma unroll
        for (int l = 0; l < 3; l++) {
            float* base = sm + l * WL_FLOATS;
            if (tid < 64) {
                base[tid] = bgv[l][tid];
                base[64 + tid] = Wg[l][tid * 65];  // t-column
            }
            for (int idx = tid; idx < 4096; idx += TPB) {
                int j = idx >> 6, k = idx & 63;
                base[128 + j * 64 + k] = Wg[l][j * 65 + 1 + k];
            }
        }
    }
    __syncthreads();

    const float t = tptr[0];
    const int r0 = blockIdx.x * ROWS_CTA + tid;
    const int r1 = r0 + TPB;

    const float* L0 = sm;
    const float* L1 = sm + WL_FLOATS;
    const float* L2 = sm + 2 * WL_FLOATS;

    float* slot = sm + W_TOTAL;                 // 256 rows x 64 floats, swizzled
    float* st0 = slot + tid * 64;
    float* st1 = slot + (tid + TPB) * 64;
    const int rm = tid & 15;                    // (tid+128)&15 == tid&15

    ull mA0 = 0ull, mB0 = 0ull;   // relu masks layer0 (row0,row1)
    ull mA1 = 0ull, mB1 = 0ull;   // relu masks layer1

    // ---- Forward ----
    {
        float2 x0[32], x1[32];
        {
            const float4* zp0 = (const float4*)(z + (size_t)r0 * 64);
            const float4* zp1 = (const float4*)(z + (size_t)r1 * 64);
#pragma unroll
            for (int i = 0; i < 16; i++) {
                float4 v0 = zp0[i], v1 = zp1[i];
                x0[2 * i] = make_float2(v0.x, v0.y); x0[2 * i + 1] = make_float2(v0.z, v0.w);
                x1[2 * i] = make_float2(v1.x, v1.y); x1[2 * i + 1] = make_float2(v1.z, v1.w);
            }
        }
        matvec_seq_dual(L0 + 128, L0, L0 + 64, t, x0, x1, st0, st1, rm, mA0, mB0);
#pragma unroll
        for (int q = 0; q < 32; q++) {
            int off = st_pair_off(rm, q);
            x0[q] = *(const float2*)(st0 + off);
            x1[q] = *(const float2*)(st1 + off);
        }
        matvec_seq_dual(L1 + 128, L1, L1 + 64, t, x0, x1, st0, st1, rm, mA1, mB1);

        ull h0[32], h1[32];
#pragma unroll
        for (int q = 0; q < 32; q++) {
            int off = st_pair_off(rm, q);
            h0[q] = *(const ull*)(st0 + off);
            h1[q] = *(const ull*)(st1 + off);
        }
        matvec_dot_dual<1>(L2 + 128, L2, L2 + 64, t, h0, h1, st0, st1, rm);  // z_dot
    }

    // ---- Coalesced z_dot flush ----
    __syncthreads();
    {
        float4* dst = (float4*)(zdot + (size_t)blockIdx.x * ROWS_CTA * 64);
        for (int i4 = tid; i4 < ROWS_CTA * 16; i4 += TPB) {
            int r = i4 >> 4, c4 = i4 & 15;
            dst[i4] = *(const float4*)(slot + r * 64 + ((c4 ^ (r & 15)) << 2));
        }
    }
    __syncthreads();

    // ---- Backward: chain  u = W0c e ; D0 ; W1c ; D1 ; W2c ; dot with e ----
    {
        ull xp0[32], xp1[32];
        {
            const float4* e0 = (const float4*)(e + (size_t)r0 * 64);
            const float4* e1 = (const float4*)(e + (size_t)r1 * 64);
#pragma unroll
            for (int i = 0; i < 16; i++) {
                float4 v0 = e0[i], v1 = e1[i];
                xp0[2 * i] = pack2(v0.x, v0.y); xp0[2 * i + 1] = pack2(v0.z, v0.w);
                xp1[2 * i] = pack2(v1.x, v1.y); xp1[2 * i + 1] = pack2(v1.z, v1.w);
            }
        }
        matvec_dot_dual<0>(L0 + 128, L0, L0 + 64, 0.0f, xp0, xp1, st0, st1, rm);   // u
#pragma unroll
        for (int q = 0; q < 32; q++) {
            int off = st_pair_off(rm, q);
            xp0[q] = maskpair(*(const ull*)(st0 + off), mA0, q);
            xp1[q] = maskpair(*(const ull*)(st1 + off), mB0, q);
        }
        matvec_dot_dual<0>(L1 + 128, L1, L1 + 64, 0.0f, xp0, xp1, st0, st1, rm);   // y
#pragma unroll
        for (int q = 0; q < 32; q++) {
            int off = st_pair_off(rm, q);
            xp0[q] = maskpair(*(const ull*)(st0 + off), mA1, q);
            xp1[q] = maskpair(*(const ull*)(st1 + off), mB1, q);
        }
        matvec_dot_dual<0>(L2 + 128, L2, L2 + 64, 0.0f, xp0, xp1, st0, st1, rm);   // p

        // div = e . p   (e re-read; L2-resident from earlier read)
        ull dp0 = 0ull, dp1 = 0ull;
        {
            const float4* e0 = (const float4*)(e + (size_t)r0 * 64);
            const float4* e1 = (const float4*)(e + (size_t)r1 * 64);
#pragma unroll
            for (int i = 0; i < 16; i++) {
                float4 v0 = e0[i], v1 = e1[i];
                int offa = st_pair_off(rm, 2 * i);
                int offb = st_pair_off(rm, 2 * i + 1);
                ffma2(dp0, pack2(v0.x, v0.y), *(const ull*)(st0 + offa));
                ffma2(dp0, pack2(v0.z, v0.w), *(const ull*)(st0 + offb));
                ffma2(dp1, pack2(v1.x, v1.y), *(const ull*)(st1 + offa));
                ffma2(dp1, pack2(v1.z, v1.w), *(const ull*)(st1 + offb));
            }
        }
        negdiv[r0] = -pairsum(dp0);
        negdiv[r1] = -pairsum(dp1);
    }
}

extern "C" void kernel_launch(void* const* d_in, const int* in_sizes, int n_in,
                              void* d_out, int out_size) {
    const float* t  = (const float*)d_in[0];
    const float* z  = (const float*)d_in[1];
    const float* e  = (const float*)d_in[2];
    const float* W0 = (const float*)d_in[3];
    const float* b0 = (const float*)d_in[4];
    const float* W1 = (const float*)d_in[5];
    const float* b1 = (const float*)d_in[6];
    const float* W2 = (const float*)d_in[7];
    const float* b2 = (const float*)d_in[8];

    float* zdot = (float*)d_out;                       // [B, 64]
    float* negdiv = zdot + (size_t)B_TOTAL * 64;       // [B, 1]

    cudaFuncSetAttribute(ode_kernel, cudaFuncAttributeMaxDynamicSharedMemorySize, SMEM_BYTES);
    ode_kernel<<<NBLK, TPB, SMEM_BYTES>>>(t, z, e, W0, b0, W1, b1, W2, b2, zdot, negdiv);
}

// round 8
// speedup vs baseline: 1.3268x; 1.3268x over previous
#include <cuda_runtime.h>

#define B_TOTAL 262144
#define TPB 128
#define ROWS_CTA 256
#define NBLK (B_TOTAL / ROWS_CTA)          // 1024

// smem: Wf[3][64][64] (12288 floats) + staging slot 256 rows x stride 65.
// Pad cell slot[r*65+64] (r = l*64+j, r<192) holds bias_l[j].
#define W_TOTAL 12288
#define ST_STRIDE 65
#define SLOT_FLOATS (ROWS_CTA * ST_STRIDE)   // 16640
#define SMEM_FLOATS (W_TOTAL + SLOT_FLOATS)  // 28928
#define SMEM_BYTES (SMEM_FLOATS * 4)         // 115712 B -> 2 CTAs/SM exact fit

typedef unsigned long long ull;

__device__ __forceinline__ void ffma2(ull& d, ull a, ull b) {
    asm("fma.rn.f32x2 %0, %1, %2, %0;" : "+l"(d) : "l"(a), "l"(b));
}
__device__ __forceinline__ float pairsum(ull v) {
    float lo, hi;
    asm("mov.b64 {%0, %1}, %2;" : "=f"(lo), "=f"(hi) : "l"(v));
    return lo + hi;
}
__device__ __forceinline__ ull pack2(float lo, float hi) {
    ull r;
    asm("mov.b64 %0, {%1, %2};" : "=l"(r) : "f"(lo), "f"(hi));
    return r;
}
// Zero pair lanes per relu-mask bits (2q, 2q+1).
__device__ __forceinline__ ull maskpair(ull v, ull m, int q) {
    ull mm = (((m >> (2 * q)) & 1ull) * 0x00000000FFFFFFFFull)
           | (((m >> (2 * q + 1)) & 1ull) * 0xFFFFFFFF00000000ull);
    return v & mm;
}

// ---------------------------------------------------------------------------
// Dual-row sequential matvec (cuBLAS-exact rounding, mask-determining).
// Per-row chain bit-identical to R3..R7: a = t*W[j][0] (c0 via uniform __ldg),
// fmaf k-ascending over smem weights, s = a + bias (bias from staging pad cell).
// Staging writes are 32-bit, immediate-offset (stride-65, conflict-free).
// ---------------------------------------------------------------------------
__device__ __forceinline__ void matvec_seq_dual(
    const float* __restrict__ Wf,      // [64][64] row-major smem
    const float* __restrict__ Wfull,   // gmem W [64][65] (t-column source)
    const float* __restrict__ biasp,   // smem pad base: bias[j] at biasp[j*65]
    float t,
    const float2* __restrict__ x0, const float2* __restrict__ x1,
    float* __restrict__ st0, float* __restrict__ st1,
    ull& m0, ull& m1) {
#pragma unroll 2
    for (int j = 0; j < 64; j += 2) {
        float c0a = __ldg(Wfull + j * 65);
        float c0b = __ldg(Wfull + (j + 1) * 65);
        float a00 = t * c0a, a01 = t * c0b;
        float a10 = t * c0a, a11 = t * c0b;
        const float4* w0 = (const float4*)(Wf + j * 64);
        const float4* w1 = (const float4*)(Wf + (j + 1) * 64);
#pragma unroll
        for (int q = 0; q < 16; q++) {
            float4 v0 = w0[q];
            float4 v1 = w1[q];
            float2 xa0 = x0[2 * q], xb0 = x0[2 * q + 1];
            float2 xa1 = x1[2 * q], xb1 = x1[2 * q + 1];
            a00 = fmaf(xa0.x, v0.x, a00); a00 = fmaf(xa0.y, v0.y, a00);
            a00 = fmaf(xb0.x, v0.z, a00); a00 = fmaf(xb0.y, v0.w, a00);
            a01 = fmaf(xa0.x, v1.x, a01); a01 = fmaf(xa0.y, v1.y, a01);
            a01 = fmaf(xb0.x, v1.z, a01); a01 = fmaf(xb0.y, v1.w, a01);
            a10 = fmaf(xa1.x, v0.x, a10); a10 = fmaf(xa1.y, v0.y, a10);
            a10 = fmaf(xb1.x, v0.z, a10); a10 = fmaf(xb1.y, v0.w, a10);
            a11 = fmaf(xa1.x, v1.x, a11); a11 = fmaf(xa1.y, v1.y, a11);
            a11 = fmaf(xb1.x, v1.z, a11); a11 = fmaf(xb1.y, v1.w, a11);
        }
        float ba = biasp[j * ST_STRIDE];
        float bb = biasp[(j + 1) * ST_STRIDE];
        float s00 = a00 + ba, s01 = a01 + bb;
        float s10 = a10 + ba, s11 = a11 + bb;
        if (s00 > 0.0f) m0 |= (1ull << j); else s00 = 0.0f;
        if (s01 > 0.0f) m0 |= (1ull << (j + 1)); else s01 = 0.0f;
        if (s10 > 0.0f) m1 |= (1ull << j); else s10 = 0.0f;
        if (s11 > 0.0f) m1 |= (1ull << (j + 1)); else s11 = 0.0f;
        st0[j] = s00; st0[j + 1] = s01;
        st1[j] = s10; st1[j + 1] = s11;
    }
}

// ---------------------------------------------------------------------------
// Dual-row FFMA2 dot matvec (continuous paths): out = W x (+ bias + t*c0).
// ---------------------------------------------------------------------------
template <int WITH_AFFINE>
__device__ __forceinline__ void matvec_dot_dual(
    const float* __restrict__ Wf,
    const float* __restrict__ Wfull,   // gmem (t-column) -- only if WITH_AFFINE
    const float* __restrict__ biasp,   // smem pads       -- only if WITH_AFFINE
    float t,
    const ull* __restrict__ x0, const ull* __restrict__ x1,
    float* __restrict__ st0, float* __restrict__ st1) {
#pragma unroll 1
    for (int j = 0; j < 64; j += 2) {
        ull a00 = 0ull, a01 = 0ull, a10 = 0ull, a11 = 0ull;
        const ulonglong2* w0 = (const ulonglong2*)(Wf + j * 64);
        const ulonglong2* w1 = (const ulonglong2*)(Wf + (j + 1) * 64);
#pragma unroll
        for (int q = 0; q < 16; q++) {
            ulonglong2 v0 = w0[q];
            ulonglong2 v1 = w1[q];
            ffma2(a00, v0.x, x0[2 * q]); ffma2(a00, v0.y, x0[2 * q + 1]);
            ffma2(a01, v1.x, x0[2 * q]); ffma2(a01, v1.y, x0[2 * q + 1]);
            ffma2(a10, v0.x, x1[2 * q]); ffma2(a10, v0.y, x1[2 * q + 1]);
            ffma2(a11, v1.x, x1[2 * q]); ffma2(a11, v1.y, x1[2 * q + 1]);
        }
        float s00 = pairsum(a00), s01 = pairsum(a01);
        float s10 = pairsum(a10), s11 = pairsum(a11);
        if (WITH_AFFINE) {
            float b0j = biasp[j * ST_STRIDE] + t * __ldg(Wfull + j * 65);
            float b1j = biasp[(j + 1) * ST_STRIDE] + t * __ldg(Wfull + (j + 1) * 65);
            s00 += b0j; s01 += b1j; s10 += b0j; s11 += b1j;
        }
        st0[j] = s00; st0[j + 1] = s01;
        st1[j] = s10; st1[j + 1] = s11;
    }
}

__global__ void __launch_bounds__(TPB)
ode_kernel(const float* __restrict__ tptr, const float* __restrict__ z,
           const float* __restrict__ e,
           const float* __restrict__ W0, const float* __restrict__ b0,
           const float* __restrict__ W1, const float* __restrict__ b1,
           const float* __restrict__ W2, const float* __restrict__ b2,
           float* __restrict__ zdot, float* __restrict__ negdiv) {
    extern __shared__ float sm[];
    const int tid = threadIdx.x;
    float* slot = sm + W_TOTAL;                 // 256 rows x 65 floats

    // ---- Stage weights; bias values go to staging pad cells slot[r*65+64] ----
    {
        const float* Wg[3] = {W0, W1, W2};
#pragma unroll
        for (int l = 0; l < 3; l++) {
            float* base = sm + l * 4096;
            for (int idx = tid; idx < 4096; idx += TPB) {
                int j = idx >> 6, k = idx & 63;
                base[j * 64 + k] = Wg[l][j * 65 + 1 + k];
            }
        }
        if (tid < 64)       slot[tid * ST_STRIDE + 64] = b0[tid];
        else if (tid < 128) slot[tid * ST_STRIDE + 64] = b1[tid - 64];
        // tid 128..191 handled below (TPB=128): rows 128..191 pads get b2
    }
    // second pass for b2 pads (rows 128..191) using tid 0..63
    if (tid < 64) slot[(128 + tid) * ST_STRIDE + 64] = b2[tid];
    __syncthreads();

    const float t = tptr[0];
    const int r0 = blockIdx.x * ROWS_CTA + tid;
    const int r1 = r0 + TPB;

    const float* L0 = sm;
    const float* L1 = sm + 4096;
    const float* L2 = sm + 2 * 4096;
    const float* B0p = slot + 64;                          // bias_l0[j] at [j*65]
    const float* B1p = slot + 64 * ST_STRIDE + 64;
    const float* B2p = slot + 128 * ST_STRIDE + 64;

    float* st0 = slot + tid * ST_STRIDE;
    float* st1 = slot + (tid + TPB) * ST_STRIDE;

    ull mA0 = 0ull, mB0 = 0ull;   // relu masks layer0 (row0,row1)
    ull mA1 = 0ull, mB1 = 0ull;   // relu masks layer1

    // ---- Forward ----
    {
        float2 x0[32], x1[32];
        {
            const float4* zp0 = (const float4*)(z + (size_t)r0 * 64);
            const float4* zp1 = (const float4*)(z + (size_t)r1 * 64);
#pragma unroll
            for (int i = 0; i < 16; i++) {
                float4 v0 = zp0[i], v1 = zp1[i];
                x0[2 * i] = make_float2(v0.x, v0.y); x0[2 * i + 1] = make_float2(v0.z, v0.w);
                x1[2 * i] = make_float2(v1.x, v1.y); x1[2 * i + 1] = make_float2(v1.z, v1.w);
            }
        }
        matvec_seq_dual(L0, W0, B0p, t, x0, x1, st0, st1, mA0, mB0);
#pragma unroll
        for (int q = 0; q < 32; q++) {
            x0[q] = make_float2(st0[2 * q], st0[2 * q + 1]);
            x1[q] = make_float2(st1[2 * q], st1[2 * q + 1]);
        }
        matvec_seq_dual(L1, W1, B1p, t, x0, x1, st0, st1, mA1, mB1);

        ull h0[32], h1[32];
#pragma unroll
        for (int q = 0; q < 32; q++) {
            h0[q] = pack2(st0[2 * q], st0[2 * q + 1]);
            h1[q] = pack2(st1[2 * q], st1[2 * q + 1]);
        }
        matvec_dot_dual<1>(L2, W2, B2p, t, h0, h1, st0, st1);  // z_dot staged
    }

    // ---- Coalesced z_dot flush (32-bit LDS gather; stride-65) ----
    __syncthreads();
    {
        float4* dst = (float4*)(zdot + (size_t)blockIdx.x * ROWS_CTA * 64);
        for (int i4 = tid; i4 < ROWS_CTA * 16; i4 += TPB) {
            int r = i4 >> 4, c = (i4 & 15) << 2;
            const float* p = slot + r * ST_STRIDE + c;
            dst[i4] = make_float4(p[0], p[1], p[2], p[3]);
        }
    }
    __syncthreads();

    // ---- Backward: chain  u = W0c e ; D0 ; W1c ; D1 ; W2c ; dot with e ----
    {
        ull xp0[32], xp1[32];
        {
            const float4* e0 = (const float4*)(e + (size_t)r0 * 64);
            const float4* e1 = (const float4*)(e + (size_t)r1 * 64);
#pragma unroll
            for (int i = 0; i < 16; i++) {
                float4 v0 = e0[i], v1 = e1[i];
                xp0[2 * i] = pack2(v0.x, v0.y); xp0[2 * i + 1] = pack2(v0.z, v0.w);
                xp1[2 * i] = pack2(v1.x, v1.y); xp1[2 * i + 1] = pack2(v1.z, v1.w);
            }
        }
        matvec_dot_dual<0>(L0, W0, B0p, 0.0f, xp0, xp1, st0, st1);   // u
#pragma unroll
        for (int q = 0; q < 32; q++) {
            xp0[q] = maskpair(pack2(st0[2 * q], st0[2 * q + 1]), mA0, q);
            xp1[q] = maskpair(pack2(st1[2 * q], st1[2 * q + 1]), mB0, q);
        }
        matvec_dot_dual<0>(L1, W1, B1p, 0.0f, xp0, xp1, st0, st1);   // y
#pragma unroll
        for (int q = 0; q < 32; q++) {
            xp0[q] = maskpair(pack2(st0[2 * q], st0[2 * q + 1]), mA1, q);
            xp1[q] = maskpair(pack2(st1[2 * q], st1[2 * q + 1]), mB1, q);
        }
        matvec_dot_dual<0>(L2, W2, B2p, 0.0f, xp0, xp1, st0, st1);   // p (staged)

        // div = e . p   (e re-read; L2-resident from earlier read)
        ull dp0 = 0ull, dp1 = 0ull;
        {
            const float4* e0 = (const float4*)(e + (size_t)r0 * 64);
            const float4* e1 = (const float4*)(e + (size_t)r1 * 64);
#pragma unroll
            for (int i = 0; i < 16; i++) {
                float4 v0 = e0[i], v1 = e1[i];
                ffma2(dp0, pack2(v0.x, v0.y), pack2(st0[4 * i], st0[4 * i + 1]));
                ffma2(dp0, pack2(v0.z, v0.w), pack2(st0[4 * i + 2], st0[4 * i + 3]));
                ffma2(dp1, pack2(v1.x, v1.y), pack2(st1[4 * i], st1[4 * i + 1]));
                ffma2(dp1, pack2(v1.z, v1.w), pack2(st1[4 * i + 2], st1[4 * i + 3]));
            }
        }
        negdiv[r0] = -pairsum(dp0);
        negdiv[r1] = -pairsum(dp1);
    }
}

extern "C" void kernel_launch(void* const* d_in, const int* in_sizes, int n_in,
                              void* d_out, int out_size) {
    const float* t  = (const float*)d_in[0];
    const float* z  = (const float*)d_in[1];
    const float* e  = (const float*)d_in[2];
    const float* W0 = (const float*)d_in[3];
    const float* b0 = (const float*)d_in[4];
    const float* W1 = (const float*)d_in[5];
    const float* b1 = (const float*)d_in[6];
    const float* W2 = (const float*)d_in[7];
    const float* b2 = (const float*)d_in[8];

    float* zdot = (float*)d_out;                       // [B, 64]
    float* negdiv = zdot + (size_t)B_TOTAL * 64;       // [B, 1]

    cudaFuncSetAttribute(ode_kernel, cudaFuncAttributeMaxDynamicSharedMemorySize, SMEM_BYTES);
    ode_kernel<<<NBLK, TPB, SMEM_BYTES>>>(t, z, e, W0, b0, W1, b1, W2, b2, zdot, negdiv);
}

// round 10
// speedup vs baseline: 1.6255x; 1.2251x over previous
#include <cuda_runtime.h>

#define B_TOTAL 262144
#define TPB 128
#define ROWS_CTA 256
#define NBLK (B_TOTAL / ROWS_CTA)          // 1024

// smem: Wf[3][64][64] (12288 floats) + staging slot 256 rows x stride 65.
// Pad cell slot[r*65+64] (r = l*64+j, r<192) holds bias_l[j].
#define W_TOTAL 12288
#define ST_STRIDE 65
#define SLOT_FLOATS (ROWS_CTA * ST_STRIDE)   // 16640
#define SMEM_FLOATS (W_TOTAL + SLOT_FLOATS)  // 28928
#define SMEM_BYTES (SMEM_FLOATS * 4)         // 115712 B -> 2 CTAs/SM (proven in R8)

typedef unsigned long long ull;

__device__ __forceinline__ void ffma2(ull& d, ull a, ull b) {
    asm("fma.rn.f32x2 %0, %1, %2, %0;" : "+l"(d) : "l"(a), "l"(b));
}
__device__ __forceinline__ float pairsum(ull v) {
    float lo, hi;
    asm("mov.b64 {%0, %1}, %2;" : "=f"(lo), "=f"(hi) : "l"(v));
    return lo + hi;
}
__device__ __forceinline__ ull pack2(float lo, float hi) {
    ull r;
    asm("mov.b64 %0, {%1, %2};" : "=l"(r) : "f"(lo), "f"(hi));
    return r;
}
// Zero pair lanes per mask bits (2q, 2q+1) of m.
__device__ __forceinline__ ull maskpair(ull v, ull m, int q) {
    ull mm = (((m >> (2 * q)) & 1ull) * 0x00000000FFFFFFFFull)
           | (((m >> (2 * q + 1)) & 1ull) * 0xFFFFFFFF00000000ull);
    return v & mm;
}

// ---------------------------------------------------------------------------
// Dual-row sequential matvec (cuBLAS-exact rounding, mask-determining).
// Identical numerics to R8 (verified bit-exact): a = t*c0 (uniform __ldg),
// fmaf k-ascending over smem weights, s = a + bias (staging pad cell).
// ---------------------------------------------------------------------------
__device__ __forceinline__ void matvec_seq_dual(
    const float* __restrict__ Wf, const float* __restrict__ Wfull,
    const float* __restrict__ biasp, float t,
    const float2* __restrict__ x0, const float2* __restrict__ x1,
    float* __restrict__ st0, float* __restrict__ st1,
    ull& m0, ull& m1) {
#pragma unroll 2
    for (int j = 0; j < 64; j += 2) {
        float c0a = __ldg(Wfull + j * 65);
        float c0b = __ldg(Wfull + (j + 1) * 65);
        float a00 = t * c0a, a01 = t * c0b;
        float a10 = t * c0a, a11 = t * c0b;
        const float4* w0 = (const float4*)(Wf + j * 64);
        const float4* w1 = (const float4*)(Wf + (j + 1) * 64);
#pragma unroll
        for (int q = 0; q < 16; q++) {
            float4 v0 = w0[q];
            float4 v1 = w1[q];
            float2 xa0 = x0[2 * q], xb0 = x0[2 * q + 1];
            float2 xa1 = x1[2 * q], xb1 = x1[2 * q + 1];
            a00 = fmaf(xa0.x, v0.x, a00); a00 = fmaf(xa0.y, v0.y, a00);
            a00 = fmaf(xb0.x, v0.z, a00); a00 = fmaf(xb0.y, v0.w, a00);
            a01 = fmaf(xa0.x, v1.x, a01); a01 = fmaf(xa0.y, v1.y, a01);
            a01 = fmaf(xb0.x, v1.z, a01); a01 = fmaf(xb0.y, v1.w, a01);
            a10 = fmaf(xa1.x, v0.x, a10); a10 = fmaf(xa1.y, v0.y, a10);
            a10 = fmaf(xb1.x, v0.z, a10); a10 = fmaf(xb1.y, v0.w, a10);
            a11 = fmaf(xa1.x, v1.x, a11); a11 = fmaf(xa1.y, v1.y, a11);
            a11 = fmaf(xb1.x, v1.z, a11); a11 = fmaf(xb1.y, v1.w, a11);
        }
        float ba = biasp[j * ST_STRIDE];
        float bb = biasp[(j + 1) * ST_STRIDE];
        float s00 = a00 + ba, s01 = a01 + bb;
        float s10 = a10 + ba, s11 = a11 + bb;
        if (s00 > 0.0f) m0 |= (1ull << j); else s00 = 0.0f;
        if (s01 > 0.0f) m0 |= (1ull << (j + 1)); else s01 = 0.0f;
        if (s10 > 0.0f) m1 |= (1ull << j); else s10 = 0.0f;
        if (s11 > 0.0f) m1 |= (1ull << (j + 1)); else s11 = 0.0f;
        st0[j] = s00; st0[j + 1] = s01;
        st1[j] = s10; st1[j + 1] = s11;
    }
}

// ---------------------------------------------------------------------------
// Dual-row FFMA2 full-input dot matvec (forward layer 2). Inputs in regs.
// ---------------------------------------------------------------------------
__device__ __forceinline__ void matvec_dot_dual_affine(
    const float* __restrict__ Wf, const float* __restrict__ Wfull,
    const float* __restrict__ biasp, float t,
    const ull* __restrict__ x0, const ull* __restrict__ x1,
    float* __restrict__ st0, float* __restrict__ st1) {
#pragma unroll 1
    for (int j = 0; j < 64; j += 2) {
        ull a00 = 0ull, a01 = 0ull, a10 = 0ull, a11 = 0ull;
        const ulonglong2* w0 = (const ulonglong2*)(Wf + j * 64);
        const ulonglong2* w1 = (const ulonglong2*)(Wf + (j + 1) * 64);
#pragma unroll
        for (int q = 0; q < 16; q++) {
            ulonglong2 v0 = w0[q];
            ulonglong2 v1 = w1[q];
            ffma2(a00, v0.x, x0[2 * q]); ffma2(a00, v0.y, x0[2 * q + 1]);
            ffma2(a01, v1.x, x0[2 * q]); ffma2(a01, v1.y, x0[2 * q + 1]);
            ffma2(a10, v0.x, x1[2 * q]); ffma2(a10, v0.y, x1[2 * q + 1]);
            ffma2(a11, v1.x, x1[2 * q]); ffma2(a11, v1.y, x1[2 * q + 1]);
        }
        float b0j = biasp[j * ST_STRIDE] + t * __ldg(Wfull + j * 65);
        float b1j = biasp[(j + 1) * ST_STRIDE] + t * __ldg(Wfull + (j + 1) * 65);
        st0[j] = pairsum(a00) + b0j; st0[j + 1] = pairsum(a01) + b1j;
        st1[j] = pairsum(a10) + b0j; st1[j + 1] = pairsum(a11) + b1j;
    }
}

// ---------------------------------------------------------------------------
// One quadrant sweep: for j in [JB, JB+32), accumulate over one k-half whose
// 16 input pairs are in regs. KC16: weight offset in 16-byte chunks (0 for
// k=0..31, 8 for k=32..63)  [R9 bug was dividing this by 2].
// STORE_MODE 0: st=ps; 1: regs p[]; 2: st=p[]+ps; 3: st=st+ps
// ---------------------------------------------------------------------------
template <int JB, int KC16, int STORE_MODE>
__device__ __forceinline__ void quad_sweep(
    const float* __restrict__ Wf,
    const ull* __restrict__ in0, const ull* __restrict__ in1,   // 16 pairs each
    float* __restrict__ st0, float* __restrict__ st1,
    float* __restrict__ p0, float* __restrict__ p1) {           // 32 floats each
#pragma unroll 2
    for (int jj = 0; jj < 32; jj += 2) {
        int j = JB + jj;
        ull a00 = 0ull, a01 = 0ull, a10 = 0ull, a11 = 0ull;
        const ulonglong2* w0 = (const ulonglong2*)(Wf + j * 64) + KC16;
        const ulonglong2* w1 = (const ulonglong2*)(Wf + (j + 1) * 64) + KC16;
#pragma unroll
        for (int q = 0; q < 8; q++) {
            ulonglong2 v0 = w0[q];
            ulonglong2 v1 = w1[q];
            ffma2(a00, v0.x, in0[2 * q]); ffma2(a00, v0.y, in0[2 * q + 1]);
            ffma2(a01, v1.x, in0[2 * q]); ffma2(a01, v1.y, in0[2 * q + 1]);
            ffma2(a10, v0.x, in1[2 * q]); ffma2(a10, v0.y, in1[2 * q + 1]);
            ffma2(a11, v1.x, in1[2 * q]); ffma2(a11, v1.y, in1[2 * q + 1]);
        }
        float s00 = pairsum(a00), s01 = pairsum(a01);
        float s10 = pairsum(a10), s11 = pairsum(a11);
        if (STORE_MODE == 0) {
            st0[j] = s00; st0[j + 1] = s01;
            st1[j] = s10; st1[j + 1] = s11;
        } else if (STORE_MODE == 1) {
            p0[jj] = s00; p0[jj + 1] = s01;
            p1[jj] = s10; p1[jj + 1] = s11;
        } else if (STORE_MODE == 2) {
            st0[j] = p0[jj] + s00; st0[j + 1] = p0[jj + 1] + s01;
            st1[j] = p1[jj] + s10; st1[j + 1] = p1[jj + 1] + s11;
        } else {
            st0[j] = st0[j] + s00; st0[j + 1] = st0[j + 1] + s01;
            st1[j] = st1[j] + s10; st1[j + 1] = st1[j + 1] + s11;
        }
    }
}

// Quadrant-blocked chain matvec: st <- W * (mask .* st). Only 16 input pairs
// per row are register-resident at any time (spill avoidance).
__device__ __forceinline__ void chain_quad_dual(
    const float* __restrict__ Wf,
    float* __restrict__ st0, float* __restrict__ st1,
    ull im0, ull im1) {
    ull in0[16], in1[16];
    float p0[32], p1[32];
    // k-half1 from staging (masked)
#pragma unroll
    for (int q = 0; q < 16; q++) {
        in0[q] = maskpair(pack2(st0[2 * q], st0[2 * q + 1]), im0, q);
        in1[q] = maskpair(pack2(st1[2 * q], st1[2 * q + 1]), im1, q);
    }
    quad_sweep<0, 0, 0>(Wf, in0, in1, st0, st1, p0, p1);   // Q1: j1 partials -> st[0..31]
    quad_sweep<32, 0, 1>(Wf, in0, in1, st0, st1, p0, p1);  // Q2: j2 partials -> regs
    // k-half2 from staging (masked), overwriting in regs
#pragma unroll
    for (int q = 0; q < 16; q++) {
        in0[q] = maskpair(pack2(st0[32 + 2 * q], st0[33 + 2 * q]), im0, q + 16);
        in1[q] = maskpair(pack2(st1[32 + 2 * q], st1[33 + 2 * q]), im1, q + 16);
    }
    quad_sweep<32, 8, 2>(Wf, in0, in1, st0, st1, p0, p1);  // Q3: j2 final -> st[32..63]
    quad_sweep<0, 8, 3>(Wf, in0, in1, st0, st1, p0, p1);   // Q4: j1 final -> st[0..31]
}

__global__ void __launch_bounds__(TPB, 2)
ode_kernel(const float* __restrict__ tptr, const float* __restrict__ z,
           const float* __restrict__ e,
           const float* __restrict__ W0, const float* __restrict__ b0,
           const float* __restrict__ W1, const float* __restrict__ b1,
           const float* __restrict__ W2, const float* __restrict__ b2,
           float* __restrict__ zdot, float* __restrict__ negdiv) {
    extern __shared__ float sm[];
    const int tid = threadIdx.x;
    float* slot = sm + W_TOTAL;                 // 256 rows x 65 floats

    // ---- Stage weights; bias values into staging pad cells slot[r*65+64] ----
    {
        const float* Wg[3] = {W0, W1, W2};
#pragma unroll
        for (int l = 0; l < 3; l++) {
            float* base = sm + l * 4096;
            for (int idx = tid; idx < 4096; idx += TPB) {
                int j = idx >> 6, k = idx & 63;
                base[j * 64 + k] = Wg[l][j * 65 + 1 + k];
            }
        }
        if (tid < 64)       slot[tid * ST_STRIDE + 64] = b0[tid];
        else if (tid < 128) slot[tid * ST_STRIDE + 64] = b1[tid - 64];
    }
    if (tid < 64) slot[(128 + tid) * ST_STRIDE + 64] = b2[tid];
    __syncthreads();

    const float t = tptr[0];
    const int r0 = blockIdx.x * ROWS_CTA + tid;
    const int r1 = r0 + TPB;

    const float* L0 = sm;
    const float* L1 = sm + 4096;
    const float* L2 = sm + 2 * 4096;
    const float* B0p = slot + 64;
    const float* B1p = slot + 64 * ST_STRIDE + 64;
    const float* B2p = slot + 128 * ST_STRIDE + 64;

    float* st0 = slot + tid * ST_STRIDE;
    float* st1 = slot + (tid + TPB) * ST_STRIDE;

    ull mA0 = 0ull, mB0 = 0ull;   // relu masks layer0 (row0,row1)
    ull mA1 = 0ull, mB1 = 0ull;   // relu masks layer1

    // ---- Forward (identical numerics to R8 passing kernel) ----
    {
        float2 x0[32], x1[32];
        {
            const float4* zp0 = (const float4*)(z + (size_t)r0 * 64);
            const float4* zp1 = (const float4*)(z + (size_t)r1 * 64);
#pragma unroll
            for (int i = 0; i < 16; i++) {
                float4 v0 = zp0[i], v1 = zp1[i];
                x0[2 * i] = make_float2(v0.x, v0.y); x0[2 * i + 1] = make_float2(v0.z, v0.w);
                x1[2 * i] = make_float2(v1.x, v1.y); x1[2 * i + 1] = make_float2(v1.z, v1.w);
            }
        }
        matvec_seq_dual(L0, W0, B0p, t, x0, x1, st0, st1, mA0, mB0);
#pragma unroll
        for (int q = 0; q < 32; q++) {
            x0[q] = make_float2(st0[2 * q], st0[2 * q + 1]);
            x1[q] = make_float2(st1[2 * q], st1[2 * q + 1]);
        }
        matvec_seq_dual(L1, W1, B1p, t, x0, x1, st0, st1, mA1, mB1);

        ull h0[32], h1[32];
#pragma unroll
        for (int q = 0; q < 32; q++) {
            h0[q] = pack2(st0[2 * q], st0[2 * q + 1]);
            h1[q] = pack2(st1[2 * q], st1[2 * q + 1]);
        }
        matvec_dot_dual_affine(L2, W2, B2p, t, h0, h1, st0, st1);  // z_dot staged
    }

    // ---- Coalesced z_dot flush ----
    __syncthreads();
    {
        float4* dst = (float4*)(zdot + (size_t)blockIdx.x * ROWS_CTA * 64);
        for (int i4 = tid; i4 < ROWS_CTA * 16; i4 += TPB) {
            int r = i4 >> 4, c = (i4 & 15) << 2;
            const float* p = slot + r * ST_STRIDE + c;
            dst[i4] = make_float4(p[0], p[1], p[2], p[3]);
        }
    }
    __syncthreads();

    // ---- Backward: u = W0c e (gmem-fed quadrants); then masked chain ----
    {
        ull in0[16], in1[16];
        float p0[32], p1[32];
        const float4* e0 = (const float4*)(e + (size_t)r0 * 64);
        const float4* e1 = (const float4*)(e + (size_t)r1 * 64);
        // k-half1 of e from gmem
#pragma unroll
        for (int i = 0; i < 8; i++) {
            float4 v0 = e0[i], v1 = e1[i];
            in0[2 * i] = pack2(v0.x, v0.y); in0[2 * i + 1] = pack2(v0.z, v0.w);
            in1[2 * i] = pack2(v1.x, v1.y); in1[2 * i + 1] = pack2(v1.z, v1.w);
        }
        quad_sweep<0, 0, 0>(L0, in0, in1, st0, st1, p0, p1);
        quad_sweep<32, 0, 1>(L0, in0, in1, st0, st1, p0, p1);
        // k-half2 of e from gmem
#pragma unroll
        for (int i = 0; i < 8; i++) {
            float4 v0 = e0[8 + i], v1 = e1[8 + i];
            in0[2 * i] = pack2(v0.x, v0.y); in0[2 * i + 1] = pack2(v0.z, v0.w);
            in1[2 * i] = pack2(v1.x, v1.y); in1[2 * i + 1] = pack2(v1.z, v1.w);
        }
        quad_sweep<32, 8, 2>(L0, in0, in1, st0, st1, p0, p1);
        quad_sweep<0, 8, 3>(L0, in0, in1, st0, st1, p0, p1);
    }
    chain_quad_dual(L1, st0, st1, mA0, mB0);   // y = W1c (D0 u)
    chain_quad_dual(L2, st0, st1, mA1, mB1);   // p = W2c (D1 y)

    // div = e . p   (e re-read; L2-resident)
    {
        ull dp0 = 0ull, dp1 = 0ull;
        const float4* e0 = (const float4*)(e + (size_t)r0 * 64);
        const float4* e1 = (const float4*)(e + (size_t)r1 * 64);
#pragma unroll
        for (int i = 0; i < 16; i++) {
            float4 v0 = e0[i], v1 = e1[i];
            ffma2(dp0, pack2(v0.x, v0.y), pack2(st0[4 * i], st0[4 * i + 1]));
            ffma2(dp0, pack2(v0.z, v0.w), pack2(st0[4 * i + 2], st0[4 * i + 3]));
            ffma2(dp1, pack2(v1.x, v1.y), pack2(st1[4 * i], st1[4 * i + 1]));
            ffma2(dp1, pack2(v1.z, v1.w), pack2(st1[4 * i + 2], st1[4 * i + 3]));
        }
        negdiv[r0] = -pairsum(dp0);
        negdiv[r1] = -pairsum(dp1);
    }
}

extern "C" void kernel_launch(void* const* d_in, const int* in_sizes, int n_in,
                              void* d_out, int out_size) {
    const float* t  = (const float*)d_in[0];
    const float* z  = (const float*)d_in[1];
    const float* e  = (const float*)d_in[2];
    const float* W0 = (const float*)d_in[3];
    const float* b0 = (const float*)d_in[4];
    const float* W1 = (const float*)d_in[5];
    const float* b1 = (const float*)d_in[6];
    const float* W2 = (const float*)d_in[7];
    const float* b2 = (const float*)d_in[8];

    float* zdot = (float*)d_out;                       // [B, 64]
    float* negdiv = zdot + (size_t)B_TOTAL * 64;       // [B, 1]

    cudaFuncSetAttribute(ode_kernel, cudaFuncAttributeMaxDynamicSharedMemorySize, SMEM_BYTES);
    ode_kernel<<<NBLK, TPB, SMEM_BYTES>>>(t, z, e, W0, b0, W1, b1, W2, b2, zdot, negdiv);
}